// round 13
// baseline (speedup 1.0000x reference)
#include <cuda_runtime.h>

#define Bb 8
#define Nn 16384
#define Kk 256
#define Dd 20

#define TP 32            // pixels per tile (4 per warp, 8 warps)
#define PPB 128          // pixels per block
#define NTILES (PPB/TP)  // 4
#define CH (Nn/PPB)      // 128 chunks per batch
#define PS  264          // p_sm row stride (bank-safe for Phase-B A-frags)
#define MS  264          // mean_hi/lo row stride (banks 8*lane4+grp, conflict-free)
#define FS  36           // f_hi/lo row stride (banks 4*grp+lane4, conflict-free)

#define EM (Bb*Kk*Dd)    // 40960
#define ES (Bb*Kk)       // 2048

__device__ float g_partM[(long)CH * EM];   // ~21 MB
__device__ float g_partS[CH * ES];         // ~1 MB

#define OFF_MHI  0                          // [24][MS] tf32-hi of mean^T (+msq row 20)
#define OFF_MLO  (OFF_MHI + 24*MS)          // [24][MS] tf32-lo residual
#define OFF_FSM  (OFF_MLO + 24*MS)          // [TP][Dd] raw features
#define OFF_FHI  (OFF_FSM + TP*Dd)          // [TP][FS] tf32-hi features (cols 0..19)
#define OFF_FLO  (OFF_FHI + TP*FS)          // [TP][FS]
#define OFF_RINV (OFF_FLO + TP*FS)          // [TP]
#define OFF_PSM  (OFF_RINV + TP)            // [TP][PS] dots -> e (also mean scratch)
#define SMEM_FLOATS (OFF_PSM + TP*PS)       // 24096 floats = 96384 B

// ---- packed f32x2 + tf32 MMA helpers ----
typedef unsigned long long u64;

#define C_NEG2  0xC0000000C0000000ULL   // {-2.0f, -2.0f}
#define C_NL2E  0xBFB8AA3BBFB8AA3BULL   // {-log2(e), -log2(e)}

__device__ __forceinline__ u64 pack2(float v) {
    u64 r; asm("mov.b64 %0, {%1,%1};" : "=l"(r) : "f"(v)); return r;
}
__device__ __forceinline__ u64 ffma2(u64 a, u64 b, u64 c) {
    u64 d; asm("fma.rn.f32x2 %0, %1, %2, %3;" : "=l"(d) : "l"(a), "l"(b), "l"(c));
    return d;
}
__device__ __forceinline__ u64 fmul2(u64 a, u64 b) {
    u64 d; asm("mul.rn.f32x2 %0, %1, %2;" : "=l"(d) : "l"(a), "l"(b));
    return d;
}
__device__ __forceinline__ void unpk(u64 v, float& lo, float& hi) {
    asm("mov.b64 {%0,%1}, %2;" : "=f"(lo), "=f"(hi) : "l"(v));
}
__device__ __forceinline__ float ex2f(float x) {
    float r; asm("ex2.approx.f32 %0, %1;" : "=f"(r) : "f"(x)); return r;
}
__device__ __forceinline__ unsigned cvt_tf32(float f) {
    unsigned r; asm("cvt.rna.tf32.f32 %0, %1;" : "=r"(r) : "f"(f)); return r;
}
__device__ __forceinline__ float tf32f(float f) {
    return __uint_as_float(cvt_tf32(f));
}
__device__ __forceinline__ void mma_tf32(float* c, const unsigned* a, const unsigned* b) {
    asm volatile("mma.sync.aligned.m16n8k8.row.col.f32.tf32.tf32.f32 "
                 "{%0,%1,%2,%3}, {%4,%5,%6,%7}, {%8,%9}, {%0,%1,%2,%3};"
                 : "+f"(c[0]), "+f"(c[1]), "+f"(c[2]), "+f"(c[3])
                 : "r"(a[0]), "r"(a[1]), "r"(a[2]), "r"(a[3]),
                   "r"(b[0]), "r"(b[1]));
}

__global__ __launch_bounds__(256, 2)
void em_main(const float* __restrict__ gmean,
             const float* __restrict__ gfeat,
             const float* __restrict__ gvalid,
             const float* __restrict__ gadj)
{
    extern __shared__ float sm[];
    float* mhi     = sm + OFF_MHI;
    float* mlo     = sm + OFF_MLO;
    float* f_sm    = sm + OFF_FSM;
    float* f_hi    = sm + OFF_FHI;
    float* f_lo    = sm + OFF_FLO;
    float* rinv_sm = sm + OFF_RINV;
    float* p_sm    = sm + OFF_PSM;

    const int tid = threadIdx.x;
    const int kg  = tid & 31;
    const int w   = tid >> 5;
    const int b   = blockIdx.y;
    const int ch  = blockIdx.x;
    const int n0  = ch * PPB;
    const int lane4 = kg & 3, grp = kg >> 2;
    const int kb = 32 * w;

    // ---- stage raw mean into p_sm scratch, then build hi/lo tf32 split ----
    {
        const float4* mb4 = (const float4*)(gmean + (long)b * Kk * Dd);
        for (int i = tid; i < Kk * Dd / 4; i += 256) ((float4*)p_sm)[i] = mb4[i];
    }
    __syncthreads();
    {
        const int k = tid;
        float msq = 0.f;
#pragma unroll
        for (int d = 0; d < Dd; d++) {
            float m = p_sm[k * Dd + d];
            msq = fmaf(m, m, msq);
            float hi = tf32f(m);
            mhi[d * MS + k] = hi;
            mlo[d * MS + k] = tf32f(m - hi);
        }
        float hi = tf32f(msq);
        mhi[Dd * MS + k] = hi;              // row 20 = |m|^2 (A col 20 = -0.5)
        mlo[Dd * MS + k] = tf32f(msq - hi);
#pragma unroll
        for (int r = 21; r < 24; r++) { mhi[r * MS + k] = 0.f; mlo[r * MS + k] = 0.f; }
    }

    // Phase-B accumulators (tf32 MMA): warp w owns k in [32w,32w+32)
    float Cacc[2][3][4];
#pragma unroll
    for (int m = 0; m < 2; m++)
#pragma unroll
        for (int n = 0; n < 3; n++)
#pragma unroll
            for (int q = 0; q < 4; q++) Cacc[m][n][q] = 0.f;

    for (int t = 0; t < NTILES; t++) {
        const int nbase = n0 + t * TP;
        __syncthreads();   // mean prep done (t=0) / previous Phase B done

        // ---- fused feature load + hi/lo tf32 split (float4 never spans px) ----
        if (tid < TP * Dd / 4) {
            float4 fv = ((const float4*)(gfeat + ((long)b * Nn + nbase) * Dd))[tid];
            ((float4*)f_sm)[tid] = fv;
            const int e0 = 4 * tid;
            const int px = e0 / Dd, d0 = e0 - px * Dd;   // d0 in {0,4,8,12,16}
            float4 hi, lo;
            hi.x = tf32f(fv.x);  lo.x = tf32f(fv.x - hi.x);
            hi.y = tf32f(fv.y);  lo.y = tf32f(fv.y - hi.y);
            hi.z = tf32f(fv.z);  lo.z = tf32f(fv.z - hi.z);
            hi.w = tf32f(fv.w);  lo.w = tf32f(fv.w - hi.w);
            *(float4*)&f_hi[px * FS + d0] = hi;
            *(float4*)&f_lo[px * FS + d0] = lo;
        }
        __syncthreads();

        // fsq per pixel: lanes 0-3, broadcast later via shfl
        float myfsq = 0.f;
        if (kg < 4) {
            const float4* fr4 = (const float4*)&f_sm[(4 * w + kg) * Dd];
#pragma unroll
            for (int q = 0; q < 5; q++) {
                float4 fv = fr4[q];
                myfsq = fmaf(fv.x, fv.x, myfsq);
                myfsq = fmaf(fv.y, fv.y, myfsq);
                myfsq = fmaf(fv.z, fv.z, myfsq);
                myfsq = fmaf(fv.w, fv.w, myfsq);
            }
        }

        // ====== Phase A dots via split-tf32 MMA: C1[px,k] = F·Mean^T - 0.5msq ======
        float C1[2][4][4];
#pragma unroll
        for (int m = 0; m < 2; m++)
#pragma unroll
            for (int n = 0; n < 4; n++)
#pragma unroll
                for (int q = 0; q < 4; q++) C1[m][n][q] = 0.f;

#pragma unroll
        for (int ks = 0; ks < 3; ks++) {
            const int dr = 8 * ks + lane4;
            unsigned Bh[4][2], Bl[4][2];
#pragma unroll
            for (int n = 0; n < 4; n++) {
                const int col = kb + 8 * n + grp;
                Bh[n][0] = __float_as_uint(mhi[dr * MS + col]);
                Bh[n][1] = __float_as_uint(mhi[(dr + 4) * MS + col]);
                Bl[n][0] = __float_as_uint(mlo[dr * MS + col]);
                Bl[n][1] = __float_as_uint(mlo[(dr + 4) * MS + col]);
            }
#pragma unroll
            for (int m = 0; m < 2; m++) {
                const int pr = 16 * m + grp;
                const int dc = 8 * ks + lane4;
                unsigned Ah[4], Al[4];
                Ah[0] = __float_as_uint(f_hi[pr * FS + dc]);
                Ah[1] = __float_as_uint(f_hi[(pr + 8) * FS + dc]);
                Al[0] = __float_as_uint(f_lo[pr * FS + dc]);
                Al[1] = __float_as_uint(f_lo[(pr + 8) * FS + dc]);
                if (ks < 2) {
                    Ah[2] = __float_as_uint(f_hi[pr * FS + dc + 4]);
                    Ah[3] = __float_as_uint(f_hi[(pr + 8) * FS + dc + 4]);
                    Al[2] = __float_as_uint(f_lo[pr * FS + dc + 4]);
                    Al[3] = __float_as_uint(f_lo[(pr + 8) * FS + dc + 4]);
                } else {   // dc+4 in 20..23: col 20 = -0.5 (msq coupling), 21..23 = 0
                    unsigned v = (lane4 == 0) ? 0xBF000000u : 0u;
                    Ah[2] = v;  Ah[3] = v;
                    Al[2] = 0u; Al[3] = 0u;
                }
#pragma unroll
                for (int n = 0; n < 4; n++) {
                    mma_tf32(C1[m][n], Ah, Bh[n]);   // hi*hi
                    mma_tf32(C1[m][n], Ah, Bl[n]);   // hi*lo
                    mma_tf32(C1[m][n], Al, Bh[n]);   // lo*hi
                }
            }
        }
        // store dot fragments to p_sm (c0,c1 = adjacent k -> float2)
#pragma unroll
        for (int m = 0; m < 2; m++)
#pragma unroll
            for (int n = 0; n < 4; n++) {
                const int col = kb + 8 * n + 2 * lane4;
                *(float2*)&p_sm[(16 * m + grp) * PS + col] =
                    make_float2(C1[m][n][0], C1[m][n][1]);
                *(float2*)&p_sm[(16 * m + grp + 8) * PS + col] =
                    make_float2(C1[m][n][2], C1[m][n][3]);
            }

        // prefetch px0 AND px1 valid/adjust: in flight across the sync
        const int  p0   = 4 * w;
        const long rowb = ((long)b * Nn + nbase + p0) * Kk;
        const float* vr = gvalid + rowb;
        const float* ar = gadj   + rowb;
        ulonglong2 cvv0 = *(const ulonglong2*)(vr + 4 * kg);
        ulonglong2 cvv1 = *(const ulonglong2*)(vr + 128 + 4 * kg);
        ulonglong2 caa0 = *(const ulonglong2*)(ar + 4 * kg);
        ulonglong2 caa1 = *(const ulonglong2*)(ar + 128 + 4 * kg);
        ulonglong2 dvv0 = *(const ulonglong2*)(vr + Kk + 4 * kg);
        ulonglong2 dvv1 = *(const ulonglong2*)(vr + Kk + 128 + 4 * kg);
        ulonglong2 daa0 = *(const ulonglong2*)(ar + Kk + 4 * kg);
        ulonglong2 daa1 = *(const ulonglong2*)(ar + Kk + 128 + 4 * kg);
        __syncthreads();   // all warps' dot slices visible

        // ====== epilogue: warp w owns px p0..p0+3, all 256 k (roll distance 2) ======
        float s4[4];
#pragma unroll
        for (int p = 0; p < 4; p++) {
            ulonglong2 nvv0, nvv1, naa0, naa1;
            if (p < 2) {
                const float* vrn = vr + (long)(p + 2) * Kk;
                const float* arn = ar + (long)(p + 2) * Kk;
                nvv0 = *(const ulonglong2*)(vrn + 4 * kg);
                nvv1 = *(const ulonglong2*)(vrn + 128 + 4 * kg);
                naa0 = *(const ulonglong2*)(arn + 4 * kg);
                naa1 = *(const ulonglong2*)(arn + 128 + 4 * kg);
            }
            ulonglong2 da = *(const ulonglong2*)&p_sm[(p0 + p) * PS + 4 * kg];
            ulonglong2 db = *(const ulonglong2*)&p_sm[(p0 + p) * PS + 128 + 4 * kg];

            const u64 c2 = pack2(__shfl_sync(0xffffffffu, myfsq, p));
            u64 d0 = ffma2(C_NEG2, da.x, c2);    // dist = fsq - 2(dot - msq/2)
            u64 d1 = ffma2(C_NEG2, da.y, c2);
            u64 d2 = ffma2(C_NEG2, db.x, c2);
            u64 d3 = ffma2(C_NEG2, db.y, c2);
            u64 g0 = ffma2(d0, cvv0.x, caa0.x);
            u64 g1 = ffma2(d1, cvv0.y, caa0.y);
            u64 g2 = ffma2(d2, cvv1.x, caa1.x);
            u64 g3 = ffma2(d3, cvv1.y, caa1.y);
            u64 x0 = fmul2(g0, C_NL2E);
            u64 x1 = fmul2(g1, C_NL2E);
            u64 x2 = fmul2(g2, C_NL2E);
            u64 x3 = fmul2(g3, C_NL2E);
            float xs[8];
            unpk(x0, xs[0], xs[1]);
            unpk(x1, xs[2], xs[3]);
            unpk(x2, xs[4], xs[5]);
            unpk(x3, xs[6], xs[7]);
            float e[8];
            float s = 0.f;
#pragma unroll
            for (int j = 0; j < 8; j++) { e[j] = ex2f(xs[j]); s += e[j]; }
            s4[p] = s;

            *(float4*)&p_sm[(p0 + p) * PS + 4 * kg] = make_float4(e[0], e[1], e[2], e[3]);
            *(float4*)&p_sm[(p0 + p) * PS + 128 + 4 * kg] = make_float4(e[4], e[5], e[6], e[7]);

            // roll: cur <- next1, next1 <- newly loaded (p+2)
            cvv0 = dvv0; cvv1 = dvv1; caa0 = daa0; caa1 = daa1;
            if (p < 2) { dvv0 = nvv0; dvv1 = nvv1; daa0 = naa0; daa1 = naa1; }
        }

#pragma unroll
        for (int o = 16; o > 0; o >>= 1) {
            s4[0] += __shfl_xor_sync(0xffffffffu, s4[0], o);
            s4[1] += __shfl_xor_sync(0xffffffffu, s4[1], o);
            s4[2] += __shfl_xor_sync(0xffffffffu, s4[2], o);
            s4[3] += __shfl_xor_sync(0xffffffffu, s4[3], o);
        }
        if (kg < 4) {
            float sv = (kg == 0) ? s4[0] : (kg == 1) ? s4[1] : (kg == 2) ? s4[2] : s4[3];
            rinv_sm[p0 + kg] = __fdividef(1.f, sv);
        }
        __syncthreads();

        // ====== Phase B: C[k,d] += P̂ᵀ·(diag(rinv)·F) via tf32 MMA ======
#pragma unroll
        for (int ks = 0; ks < 4; ks++) {
            const int pxb = 8 * ks;
            const float r0 = rinv_sm[pxb + lane4];
            const float r1 = rinv_sm[pxb + lane4 + 4];
            unsigned Bf[3][2];
#pragma unroll
            for (int n = 0; n < 3; n++) {
                const int d = 8 * n + grp;
                float b0, b1;
                if (d < Dd) {
                    b0 = f_sm[(pxb + lane4) * Dd + d] * r0;
                    b1 = f_sm[(pxb + lane4 + 4) * Dd + d] * r1;
                } else if (d == Dd) { b0 = r0; b1 = r1; }
                else { b0 = 0.f; b1 = 0.f; }
                Bf[n][0] = cvt_tf32(b0);
                Bf[n][1] = cvt_tf32(b1);
            }
#pragma unroll
            for (int m = 0; m < 2; m++) {
                const int krow = kb + 16 * m + grp;
                const int pxa  = pxb + lane4;
                unsigned Af[4];
                Af[0] = cvt_tf32(p_sm[pxa * PS + krow]);
                Af[1] = cvt_tf32(p_sm[pxa * PS + krow + 8]);
                Af[2] = cvt_tf32(p_sm[(pxa + 4) * PS + krow]);
                Af[3] = cvt_tf32(p_sm[(pxa + 4) * PS + krow + 8]);
#pragma unroll
                for (int n = 0; n < 3; n++)
                    mma_tf32(Cacc[m][n], Af, Bf[n]);
            }
        }
    }

    // ---- write partials from C fragments ----
#pragma unroll
    for (int m = 0; m < 2; m++) {
        const int k0 = 32 * w + 16 * m + grp;
        const int k1 = k0 + 8;
#pragma unroll
        for (int n = 0; n < 3; n++) {
            const int d0 = 8 * n + 2 * lane4;
            if (d0 < Dd) {
                *(float2*)&g_partM[(long)ch * EM + (long)((b << 8) + k0) * Dd + d0] =
                    make_float2(Cacc[m][n][0], Cacc[m][n][1]);
                *(float2*)&g_partM[(long)ch * EM + (long)((b << 8) + k1) * Dd + d0] =
                    make_float2(Cacc[m][n][2], Cacc[m][n][3]);
            } else if (d0 == Dd) {
                g_partS[ch * ES + (b << 8) + k0] = Cacc[m][n][0];
                g_partS[ch * ES + (b << 8) + k1] = Cacc[m][n][2];
            }
        }
    }
}

// Fused final reduction: thread e sums 128 coalesced partM terms; partS summed
// redundantly per-thread (<=2 distinct words per warp-load -> L2/broadcast).
__global__ void reduce_all(float* __restrict__ out)
{
    const int e  = blockIdx.x * 256 + threadIdx.x;   // EM = 40960 = 160*256
    const int bk = e / Dd;
    float m = 0.f, s = 0.f;
#pragma unroll 8
    for (int c = 0; c < CH; c++) {
        m += g_partM[(long)c * EM + e];
        s += g_partS[c * ES + bk];
    }
    out[e] = m / fmaxf(s, 1e-12f);
}

extern "C" void kernel_launch(void* const* d_in, const int* in_sizes, int n_in,
                              void* d_out, int out_size)
{
    const float* gmean  = (const float*)d_in[0];
    const float* gfeat  = (const float*)d_in[1];
    const float* gvalid = (const float*)d_in[2];
    const float* gadj   = (const float*)d_in[3];
    float* out = (float*)d_out;

    cudaFuncSetAttribute(em_main, cudaFuncAttributeMaxDynamicSharedMemorySize,
                         SMEM_FLOATS * (int)sizeof(float));

    dim3 grid(CH, Bb);
    em_main<<<grid, 256, SMEM_FLOATS * sizeof(float)>>>(gmean, gfeat, gvalid, gadj);
    reduce_all<<<EM / 256, 256>>>(out);
}

// round 14
// speedup vs baseline: 1.0564x; 1.0564x over previous
#include <cuda_runtime.h>

#define Bb 8
#define Nn 16384
#define Kk 256
#define Dd 20

#define TP 32            // pixels per tile (4 per warp, 8 warps)
#define PPB 128          // pixels per block
#define NTILES (PPB/TP)  // 4
#define CH (Nn/PPB)      // 128 chunks per batch
#define PS  264          // p_sm row stride (bank-safe for Phase-B A-frags)
#define MS  264          // mean_hi/lo row stride (banks 8*lane4+grp, conflict-free)
#define FS  36           // f_hi/lo row stride (banks 4*grp+lane4, conflict-free)

#define EM (Bb*Kk*Dd)    // 40960
#define ES (Bb*Kk)       // 2048
#define G1 16            // stage-1 reduction groups
#define CPG (CH/G1)      // 8 chunks per group

__device__ float g_partM[(long)CH * EM];   // ~21 MB
__device__ float g_partS[CH * ES];         // ~1 MB
__device__ float g_p2M[G1 * EM];
__device__ float g_p2S[G1 * ES];

#define OFF_MHI  0                          // [24][MS] tf32-hi of mean^T (+msq row 20)
#define OFF_MLO  (OFF_MHI + 24*MS)          // [24][MS] tf32-lo residual
#define OFF_FSM  (OFF_MLO + 24*MS)          // [TP][Dd] raw features
#define OFF_FHI  (OFF_FSM + TP*Dd)          // [TP][FS] tf32-hi features (cols 0..19)
#define OFF_FLO  (OFF_FHI + TP*FS)          // [TP][FS]
#define OFF_RINV (OFF_FLO + TP*FS)          // [TP]
#define OFF_PSM  (OFF_RINV + TP)            // [TP][PS] dots -> e (also mean scratch)
#define SMEM_FLOATS (OFF_PSM + TP*PS)       // 24096 floats = 96384 B

// ---- packed f32x2 + tf32 MMA helpers ----
typedef unsigned long long u64;

#define C_NEG2  0xC0000000C0000000ULL   // {-2.0f, -2.0f}
#define C_NL2E  0xBFB8AA3BBFB8AA3BULL   // {-log2(e), -log2(e)}

__device__ __forceinline__ u64 pack2(float v) {
    u64 r; asm("mov.b64 %0, {%1,%1};" : "=l"(r) : "f"(v)); return r;
}
__device__ __forceinline__ u64 ffma2(u64 a, u64 b, u64 c) {
    u64 d; asm("fma.rn.f32x2 %0, %1, %2, %3;" : "=l"(d) : "l"(a), "l"(b), "l"(c));
    return d;
}
__device__ __forceinline__ u64 fmul2(u64 a, u64 b) {
    u64 d; asm("mul.rn.f32x2 %0, %1, %2;" : "=l"(d) : "l"(a), "l"(b));
    return d;
}
__device__ __forceinline__ void unpk(u64 v, float& lo, float& hi) {
    asm("mov.b64 {%0,%1}, %2;" : "=f"(lo), "=f"(hi) : "l"(v));
}
__device__ __forceinline__ float ex2f(float x) {
    float r; asm("ex2.approx.f32 %0, %1;" : "=f"(r) : "f"(x)); return r;
}
__device__ __forceinline__ unsigned cvt_tf32(float f) {
    unsigned r; asm("cvt.rna.tf32.f32 %0, %1;" : "=r"(r) : "f"(f)); return r;
}
__device__ __forceinline__ float tf32f(float f) {
    return __uint_as_float(cvt_tf32(f));
}
__device__ __forceinline__ void mma_tf32(float* c, const unsigned* a, const unsigned* b) {
    asm volatile("mma.sync.aligned.m16n8k8.row.col.f32.tf32.tf32.f32 "
                 "{%0,%1,%2,%3}, {%4,%5,%6,%7}, {%8,%9}, {%0,%1,%2,%3};"
                 : "+f"(c[0]), "+f"(c[1]), "+f"(c[2]), "+f"(c[3])
                 : "r"(a[0]), "r"(a[1]), "r"(a[2]), "r"(a[3]),
                   "r"(b[0]), "r"(b[1]));
}

__global__ __launch_bounds__(256, 2)
void em_main(const float* __restrict__ gmean,
             const float* __restrict__ gfeat,
             const float* __restrict__ gvalid,
             const float* __restrict__ gadj)
{
    extern __shared__ float sm[];
    float* mhi     = sm + OFF_MHI;
    float* mlo     = sm + OFF_MLO;
    float* f_sm    = sm + OFF_FSM;
    float* f_hi    = sm + OFF_FHI;
    float* f_lo    = sm + OFF_FLO;
    float* rinv_sm = sm + OFF_RINV;
    float* p_sm    = sm + OFF_PSM;

    const int tid = threadIdx.x;
    const int kg  = tid & 31;
    const int w   = tid >> 5;
    const int b   = blockIdx.y;
    const int ch  = blockIdx.x;
    const int n0  = ch * PPB;
    const int lane4 = kg & 3, grp = kg >> 2;
    const int kb = 32 * w;

    // ---- stage raw mean into p_sm scratch, then build hi/lo tf32 split ----
    {
        const float4* mb4 = (const float4*)(gmean + (long)b * Kk * Dd);
        for (int i = tid; i < Kk * Dd / 4; i += 256) ((float4*)p_sm)[i] = mb4[i];
    }
    __syncthreads();
    {
        const int k = tid;
        float msq = 0.f;
#pragma unroll
        for (int d = 0; d < Dd; d++) {
            float m = p_sm[k * Dd + d];
            msq = fmaf(m, m, msq);
            float hi = tf32f(m);
            mhi[d * MS + k] = hi;
            mlo[d * MS + k] = tf32f(m - hi);
        }
        float hi = tf32f(msq);
        mhi[Dd * MS + k] = hi;              // row 20 = |m|^2 (A col 20 = -0.5)
        mlo[Dd * MS + k] = tf32f(msq - hi);
#pragma unroll
        for (int r = 21; r < 24; r++) { mhi[r * MS + k] = 0.f; mlo[r * MS + k] = 0.f; }
    }

    // Phase-B accumulators (tf32 MMA): warp w owns k in [32w,32w+32)
    float Cacc[2][3][4];
#pragma unroll
    for (int m = 0; m < 2; m++)
#pragma unroll
        for (int n = 0; n < 3; n++)
#pragma unroll
            for (int q = 0; q < 4; q++) Cacc[m][n][q] = 0.f;

    for (int t = 0; t < NTILES; t++) {
        const int nbase = n0 + t * TP;
        __syncthreads();   // mean prep done (t=0) / previous Phase B done

        // ---- fused feature load + hi/lo tf32 split (float4 never spans px) ----
        if (tid < TP * Dd / 4) {
            float4 fv = ((const float4*)(gfeat + ((long)b * Nn + nbase) * Dd))[tid];
            ((float4*)f_sm)[tid] = fv;
            const int e0 = 4 * tid;
            const int px = e0 / Dd, d0 = e0 - px * Dd;   // d0 in {0,4,8,12,16}
            float4 hi, lo;
            hi.x = tf32f(fv.x);  lo.x = tf32f(fv.x - hi.x);
            hi.y = tf32f(fv.y);  lo.y = tf32f(fv.y - hi.y);
            hi.z = tf32f(fv.z);  lo.z = tf32f(fv.z - hi.z);
            hi.w = tf32f(fv.w);  lo.w = tf32f(fv.w - hi.w);
            *(float4*)&f_hi[px * FS + d0] = hi;
            *(float4*)&f_lo[px * FS + d0] = lo;
        }
        __syncthreads();

        // fsq per pixel: lanes 0-3, broadcast later via shfl
        float myfsq = 0.f;
        if (kg < 4) {
            const float4* fr4 = (const float4*)&f_sm[(4 * w + kg) * Dd];
#pragma unroll
            for (int q = 0; q < 5; q++) {
                float4 fv = fr4[q];
                myfsq = fmaf(fv.x, fv.x, myfsq);
                myfsq = fmaf(fv.y, fv.y, myfsq);
                myfsq = fmaf(fv.z, fv.z, myfsq);
                myfsq = fmaf(fv.w, fv.w, myfsq);
            }
        }

        // ====== Phase A dots via split-tf32 MMA: C1[px,k] = F·Mean^T - 0.5msq ======
        float C1[2][4][4];
#pragma unroll
        for (int m = 0; m < 2; m++)
#pragma unroll
            for (int n = 0; n < 4; n++)
#pragma unroll
                for (int q = 0; q < 4; q++) C1[m][n][q] = 0.f;

#pragma unroll
        for (int ks = 0; ks < 3; ks++) {
            const int dr = 8 * ks + lane4;
            unsigned Bh[4][2], Bl[4][2];
#pragma unroll
            for (int n = 0; n < 4; n++) {
                const int col = kb + 8 * n + grp;
                Bh[n][0] = __float_as_uint(mhi[dr * MS + col]);
                Bh[n][1] = __float_as_uint(mhi[(dr + 4) * MS + col]);
                Bl[n][0] = __float_as_uint(mlo[dr * MS + col]);
                Bl[n][1] = __float_as_uint(mlo[(dr + 4) * MS + col]);
            }
#pragma unroll
            for (int m = 0; m < 2; m++) {
                const int pr = 16 * m + grp;
                const int dc = 8 * ks + lane4;
                unsigned Ah[4], Al[4];
                Ah[0] = __float_as_uint(f_hi[pr * FS + dc]);
                Ah[1] = __float_as_uint(f_hi[(pr + 8) * FS + dc]);
                Al[0] = __float_as_uint(f_lo[pr * FS + dc]);
                Al[1] = __float_as_uint(f_lo[(pr + 8) * FS + dc]);
                if (ks < 2) {
                    Ah[2] = __float_as_uint(f_hi[pr * FS + dc + 4]);
                    Ah[3] = __float_as_uint(f_hi[(pr + 8) * FS + dc + 4]);
                    Al[2] = __float_as_uint(f_lo[pr * FS + dc + 4]);
                    Al[3] = __float_as_uint(f_lo[(pr + 8) * FS + dc + 4]);
                } else {   // dc+4 in 20..23: col 20 = -0.5 (msq coupling), 21..23 = 0
                    unsigned v = (lane4 == 0) ? 0xBF000000u : 0u;
                    Ah[2] = v;  Ah[3] = v;
                    Al[2] = 0u; Al[3] = 0u;
                }
#pragma unroll
                for (int n = 0; n < 4; n++) {
                    mma_tf32(C1[m][n], Ah, Bh[n]);   // hi*hi
                    mma_tf32(C1[m][n], Ah, Bl[n]);   // hi*lo
                    mma_tf32(C1[m][n], Al, Bh[n]);   // lo*hi
                }
            }
        }
        // store dot fragments to p_sm (c0,c1 = adjacent k -> float2)
#pragma unroll
        for (int m = 0; m < 2; m++)
#pragma unroll
            for (int n = 0; n < 4; n++) {
                const int col = kb + 8 * n + 2 * lane4;
                *(float2*)&p_sm[(16 * m + grp) * PS + col] =
                    make_float2(C1[m][n][0], C1[m][n][1]);
                *(float2*)&p_sm[(16 * m + grp + 8) * PS + col] =
                    make_float2(C1[m][n][2], C1[m][n][3]);
            }

        // prefetch px0 AND px1 valid/adjust: in flight across the sync
        const int  p0   = 4 * w;
        const long rowb = ((long)b * Nn + nbase + p0) * Kk;
        const float* vr = gvalid + rowb;
        const float* ar = gadj   + rowb;
        ulonglong2 cvv0 = *(const ulonglong2*)(vr + 4 * kg);
        ulonglong2 cvv1 = *(const ulonglong2*)(vr + 128 + 4 * kg);
        ulonglong2 caa0 = *(const ulonglong2*)(ar + 4 * kg);
        ulonglong2 caa1 = *(const ulonglong2*)(ar + 128 + 4 * kg);
        ulonglong2 dvv0 = *(const ulonglong2*)(vr + Kk + 4 * kg);
        ulonglong2 dvv1 = *(const ulonglong2*)(vr + Kk + 128 + 4 * kg);
        ulonglong2 daa0 = *(const ulonglong2*)(ar + Kk + 4 * kg);
        ulonglong2 daa1 = *(const ulonglong2*)(ar + Kk + 128 + 4 * kg);
        __syncthreads();   // all warps' dot slices visible

        // ====== epilogue: warp w owns px p0..p0+3, all 256 k (roll distance 2) ======
        float s4[4];
#pragma unroll
        for (int p = 0; p < 4; p++) {
            ulonglong2 nvv0, nvv1, naa0, naa1;
            if (p < 2) {
                const float* vrn = vr + (long)(p + 2) * Kk;
                const float* arn = ar + (long)(p + 2) * Kk;
                nvv0 = *(const ulonglong2*)(vrn + 4 * kg);
                nvv1 = *(const ulonglong2*)(vrn + 128 + 4 * kg);
                naa0 = *(const ulonglong2*)(arn + 4 * kg);
                naa1 = *(const ulonglong2*)(arn + 128 + 4 * kg);
            }
            ulonglong2 da = *(const ulonglong2*)&p_sm[(p0 + p) * PS + 4 * kg];
            ulonglong2 db = *(const ulonglong2*)&p_sm[(p0 + p) * PS + 128 + 4 * kg];

            const u64 c2 = pack2(__shfl_sync(0xffffffffu, myfsq, p));
            u64 d0 = ffma2(C_NEG2, da.x, c2);    // dist = fsq - 2(dot - msq/2)
            u64 d1 = ffma2(C_NEG2, da.y, c2);
            u64 d2 = ffma2(C_NEG2, db.x, c2);
            u64 d3 = ffma2(C_NEG2, db.y, c2);
            u64 g0 = ffma2(d0, cvv0.x, caa0.x);
            u64 g1 = ffma2(d1, cvv0.y, caa0.y);
            u64 g2 = ffma2(d2, cvv1.x, caa1.x);
            u64 g3 = ffma2(d3, cvv1.y, caa1.y);
            u64 x0 = fmul2(g0, C_NL2E);
            u64 x1 = fmul2(g1, C_NL2E);
            u64 x2 = fmul2(g2, C_NL2E);
            u64 x3 = fmul2(g3, C_NL2E);
            float xs[8];
            unpk(x0, xs[0], xs[1]);
            unpk(x1, xs[2], xs[3]);
            unpk(x2, xs[4], xs[5]);
            unpk(x3, xs[6], xs[7]);
            float e[8];
            float s = 0.f;
#pragma unroll
            for (int j = 0; j < 8; j++) { e[j] = ex2f(xs[j]); s += e[j]; }
            s4[p] = s;

            *(float4*)&p_sm[(p0 + p) * PS + 4 * kg] = make_float4(e[0], e[1], e[2], e[3]);
            *(float4*)&p_sm[(p0 + p) * PS + 128 + 4 * kg] = make_float4(e[4], e[5], e[6], e[7]);

            // roll: cur <- next1, next1 <- newly loaded (p+2)
            cvv0 = dvv0; cvv1 = dvv1; caa0 = daa0; caa1 = daa1;
            if (p < 2) { dvv0 = nvv0; dvv1 = nvv1; daa0 = naa0; daa1 = naa1; }
        }

#pragma unroll
        for (int o = 16; o > 0; o >>= 1) {
            s4[0] += __shfl_xor_sync(0xffffffffu, s4[0], o);
            s4[1] += __shfl_xor_sync(0xffffffffu, s4[1], o);
            s4[2] += __shfl_xor_sync(0xffffffffu, s4[2], o);
            s4[3] += __shfl_xor_sync(0xffffffffu, s4[3], o);
        }
        if (kg < 4) {
            float sv = (kg == 0) ? s4[0] : (kg == 1) ? s4[1] : (kg == 2) ? s4[2] : s4[3];
            rinv_sm[p0 + kg] = __fdividef(1.f, sv);
        }
        __syncthreads();

        // ====== Phase B: C[k,d] += P̂ᵀ·(diag(rinv)·F) via tf32 MMA ======
#pragma unroll
        for (int ks = 0; ks < 4; ks++) {
            const int pxb = 8 * ks;
            const float r0 = rinv_sm[pxb + lane4];
            const float r1 = rinv_sm[pxb + lane4 + 4];
            unsigned Bf[3][2];
#pragma unroll
            for (int n = 0; n < 3; n++) {
                const int d = 8 * n + grp;
                float b0, b1;
                if (d < Dd) {
                    b0 = f_sm[(pxb + lane4) * Dd + d] * r0;
                    b1 = f_sm[(pxb + lane4 + 4) * Dd + d] * r1;
                } else if (d == Dd) { b0 = r0; b1 = r1; }
                else { b0 = 0.f; b1 = 0.f; }
                Bf[n][0] = cvt_tf32(b0);
                Bf[n][1] = cvt_tf32(b1);
            }
#pragma unroll
            for (int m = 0; m < 2; m++) {
                const int krow = kb + 16 * m + grp;
                const int pxa  = pxb + lane4;
                unsigned Af[4];
                Af[0] = cvt_tf32(p_sm[pxa * PS + krow]);
                Af[1] = cvt_tf32(p_sm[pxa * PS + krow + 8]);
                Af[2] = cvt_tf32(p_sm[(pxa + 4) * PS + krow]);
                Af[3] = cvt_tf32(p_sm[(pxa + 4) * PS + krow + 8]);
#pragma unroll
                for (int n = 0; n < 3; n++)
                    mma_tf32(Cacc[m][n], Af, Bf[n]);
            }
        }
    }

    // ---- write partials from C fragments ----
#pragma unroll
    for (int m = 0; m < 2; m++) {
        const int k0 = 32 * w + 16 * m + grp;
        const int k1 = k0 + 8;
#pragma unroll
        for (int n = 0; n < 3; n++) {
            const int d0 = 8 * n + 2 * lane4;
            if (d0 < Dd) {
                *(float2*)&g_partM[(long)ch * EM + (long)((b << 8) + k0) * Dd + d0] =
                    make_float2(Cacc[m][n][0], Cacc[m][n][1]);
                *(float2*)&g_partM[(long)ch * EM + (long)((b << 8) + k1) * Dd + d0] =
                    make_float2(Cacc[m][n][2], Cacc[m][n][3]);
            } else if (d0 == Dd) {
                g_partS[ch * ES + (b << 8) + k0] = Cacc[m][n][0];
                g_partS[ch * ES + (b << 8) + k1] = Cacc[m][n][2];
            }
        }
    }
}

// Stage 1: fold 128 chunks -> 16 groups of 8, fully coalesced, 8-deep MLP.
__global__ void reduce1()
{
    const int i = blockIdx.x * 256 + threadIdx.x;
    if (i < G1 * EM) {
        const int g = i / EM, e = i - g * EM;
        float s = 0.f;
#pragma unroll
        for (int c = 0; c < CPG; c++)
            s += g_partM[(long)(g * CPG + c) * EM + e];
        g_p2M[i] = s;
    } else {
        const int j = i - G1 * EM;
        if (j < G1 * ES) {
            const int g = j / ES, e = j - g * ES;
            float s = 0.f;
#pragma unroll
            for (int c = 0; c < CPG; c++)
                s += g_partS[(g * CPG + c) * ES + e];
            g_p2S[j] = s;
        }
    }
}

// Stage 2: final 16-way sum + normalize.
__global__ void reduce2(float* __restrict__ out)
{
    const int e = blockIdx.x * 256 + threadIdx.x;   // over EM = 40960
    if (e >= EM) return;
    const int bk = e / Dd;
    float m = 0.f, s = 0.f;
#pragma unroll
    for (int g = 0; g < G1; g++) {
        m += g_p2M[g * EM + e];
        s += g_p2S[g * ES + bk];
    }
    out[e] = m / fmaxf(s, 1e-12f);
}

extern "C" void kernel_launch(void* const* d_in, const int* in_sizes, int n_in,
                              void* d_out, int out_size)
{
    const float* gmean  = (const float*)d_in[0];
    const float* gfeat  = (const float*)d_in[1];
    const float* gvalid = (const float*)d_in[2];
    const float* gadj   = (const float*)d_in[3];
    float* out = (float*)d_out;

    cudaFuncSetAttribute(em_main, cudaFuncAttributeMaxDynamicSharedMemorySize,
                         SMEM_FLOATS * (int)sizeof(float));

    dim3 grid(CH, Bb);
    em_main<<<grid, 256, SMEM_FLOATS * sizeof(float)>>>(gmean, gfeat, gvalid, gadj);
    reduce1<<<(G1 * EM + G1 * ES + 255) / 256, 256>>>();
    reduce2<<<(EM + 255) / 256, 256>>>(out);
}